// round 17
// baseline (speedup 1.0000x reference)
#include <cuda_runtime.h>
#include <stdint.h>

#define N      1024
#define STEPS  32
#define TTOT   1900.0f
#define T0     1880.0f
#define NT     256            // threads per block
#define NB     512            // blocks (2 rows each) — co-resident: 4/SM x 148 = 592 >= 512
#define RPB    2
#define SLOTS  16
#define PERSLOT (NB / SLOTS)  // 32

// fp64 compile-time fold, then cast to fp32
#define C_FD ((float)(1e-16 * (910.0 * 9.81) * (910.0 * 9.81) * (910.0 * 9.81)))

// Scratch (device globals — no allocations allowed)
__device__ float        g_Hbuf[N * N];      // ping-pong partner of d_out
__device__ float        g_D[N * N];         // D, stride N (rows 0..1022 used)
__device__ unsigned int g_maxD[STEPS];
__device__ unsigned int g_cnt[SLOTS * 32];  // slot counters, 128B apart
__device__ unsigned int g_master;           // master arrival counter
__device__ volatile unsigned int g_release; // barrier release generation

// ---------------------------------------------------------------------------
__global__ void init_kernel(const float* __restrict__ Hinit, float* __restrict__ H0) {
    int idx = blockIdx.x * blockDim.x + threadIdx.x;
    int stride = gridDim.x * blockDim.x;
    const float4* src = (const float4*)Hinit;
    float4* dst = (float4*)H0;
    for (int i = idx; i < N * N / 4; i += stride) dst[i] = src[i];
    for (int i = idx; i < SLOTS * 32; i += stride) g_cnt[i] = 0u;
    if (idx < STEPS) g_maxD[idx] = 0u;
    if (idx == STEPS) { g_master = 0u; g_release = 0u; }
}

// ---------------------------------------------------------------------------
// Hierarchical grid barrier: blocks arrive on 16 padded slot counters (parallel
// L2 lines); each slot's completer arrives on the master; last master arrival
// publishes release. Generation-counted; reset each replay by init_kernel.
// Grid is co-resident (proven envelope NB=512 @ __launch_bounds__(256,4)).
__device__ __forceinline__ void grid_sync(unsigned int gen) {
    __syncthreads();
    if (threadIdx.x == 0) {
        __threadfence();
        unsigned int slot = blockIdx.x & (SLOTS - 1);
        unsigned int prev = atomicAdd(&g_cnt[slot * 32], 1u);
        if (prev == gen * PERSLOT - 1u) {
            unsigned int mp = atomicAdd(&g_master, 1u);
            if (mp == gen * SLOTS - 1u) {
                __threadfence();
                g_release = gen;               // last arriver releases
            } else {
                while (g_release < gen) __nanosleep(20);
            }
        } else {
            while (g_release < gen) __nanosleep(20);
        }
        __threadfence();
    }
    __syncthreads();
}

__device__ __forceinline__ float4 ld4(const float* p) {
    return *reinterpret_cast<const float4*>(p);
}

// Reference-ordered D formula
__device__ __forceinline__ float d_cell(float h00, float h01, float h10, float h11,
                                        float z00, float z01, float z10, float z11) {
    float havg = 0.25f * (h00 + h11 + h01 + h10);
    float sx = 0.5f * ((z01 - z00) / 100.0f + (z11 - z10) / 100.0f);
    float sy = 0.5f * ((z10 - z00) / 100.0f + (z11 - z01) / 100.0f);
    float sn2 = sx * sx + sy * sy + 1e-20f;
    float h2 = havg * havg;
    float h5 = h2 * h2 * havg;
    return C_FD * h5 * sn2 + 1e-20f;
}

// ---------------------------------------------------------------------------
__global__ void __launch_bounds__(NT, 4)
glacier_persist(float* __restrict__ buf0,          // = d_out
                float* __restrict__ buf1,          // = g_Hbuf
                const float* __restrict__ Zt,
                const float* __restrict__ Zela)
{
    const int tid = threadIdx.x;
    const int r0  = blockIdx.x * RPB;
    const int c0  = 4 * tid;

    __shared__ unsigned int s_max;
    float t = T0;
    unsigned int gen = 0;

    for (int s = 0; s < STEPS; s++) {
        // -------- early exit: dt == 0 for all remaining steps (identity) ------
        if (!(t < TTOT)) {
            if (s & 1) {
                #pragma unroll
                for (int rr = 0; rr < RPB; rr++) {
                    int r = r0 + rr;
                    *(float4*)&buf0[r * N + c0] = ld4(&buf1[r * N + c0]);
                }
            }
            return;
        }

        const float* Hc = (s & 1) ? buf1 : buf0;
        float*       Hn = (s & 1) ? buf0 : buf1;

        if (tid == 0) s_max = 0u;
        __syncthreads();

        // ---------------- Phase A: rows r0..r0+2 once; D rows r0, r0+1 -------
        float h[3][5], zs[3][5];            // cols c0 .. c0+4 (right seam incl.)
        #pragma unroll
        for (int lr = 0; lr < 3; lr++) {
            int r = r0 + lr;                // r0 <= 1022, so r <= 1024
            float4 hv = make_float4(0.f, 0.f, 0.f, 0.f);
            float4 zv = hv;
            float h4 = 0.f, z4 = 0.f;
            if (r < N) {
                hv = ld4(&Hc[r * N + c0]);
                zv = ld4(&Zt[r * N + c0]);
                if (tid < NT - 1) { h4 = Hc[r * N + c0 + 4]; z4 = Zt[r * N + c0 + 4]; }
            }
            h[lr][0] = hv.x; zs[lr][0] = zv.x + hv.x;
            h[lr][1] = hv.y; zs[lr][1] = zv.y + hv.y;
            h[lr][2] = hv.z; zs[lr][2] = zv.z + hv.z;
            h[lr][3] = hv.w; zs[lr][3] = zv.w + hv.w;
            h[lr][4] = h4;   zs[lr][4] = z4 + h4;
        }

        float dv[2][4];
        unsigned int lmax = 0u;
        #pragma unroll
        for (int dr = 0; dr < 2; dr++) {
            int r = r0 + dr;
            if (r <= N - 2) {
                #pragma unroll
                for (int j = 0; j < 4; j++)
                    dv[dr][j] = d_cell(h[dr][j], h[dr][j + 1], h[dr + 1][j], h[dr + 1][j + 1],
                                       zs[dr][j], zs[dr][j + 1], zs[dr + 1][j], zs[dr + 1][j + 1]);
                if (tid == NT - 1) dv[dr][3] = 0.0f;   // col 1023 not a D cell
                #pragma unroll
                for (int j = 0; j < 4; j++) {
                    unsigned int db = __float_as_uint(dv[dr][j]);
                    if (db > lmax) lmax = db;
                }
                *(float4*)&g_D[r * N + c0] =
                    make_float4(dv[dr][0], dv[dr][1], dv[dr][2], dv[dr][3]);
            } else {
                #pragma unroll
                for (int j = 0; j < 4; j++) dv[dr][j] = 0.0f;  // unused
            }
        }
        unsigned int wmax = __reduce_max_sync(0xffffffffu, lmax);
        if ((tid & 31) == 0) atomicMax(&s_max, wmax);
        __syncthreads();
        if (tid == 0) atomicMax(&g_maxD[s], s_max);

        grid_sync(++gen);

        // ---------------- Phase B: H update (reuses h/zs/dv registers) -------
        float maxD = __uint_as_float(g_maxD[s]);
        float dt = fminf(10000.0f / (2.7f * maxD), 1.0f);

        // extra data: row r0-1 (zu for row r0), D halo row r0-1, left seams
        float zu0[4] = {0.f, 0.f, 0.f, 0.f};
        float dP[4]  = {0.f, 0.f, 0.f, 0.f};  // D[r0-1], cols c0..c0+3
        float dPl = 0.f;                       // D[r0-1][c0-1]
        if (r0 > 0) {
            float4 hM = ld4(&Hc[(r0 - 1) * N + c0]);
            float4 zM = ld4(&Zt[(r0 - 1) * N + c0]);
            zu0[0] = zM.x + hM.x; zu0[1] = zM.y + hM.y;
            zu0[2] = zM.z + hM.z; zu0[3] = zM.w + hM.w;
            float4 dPv = ld4(&g_D[(r0 - 1) * N + c0]);
            dP[0] = dPv.x; dP[1] = dPv.y; dP[2] = dPv.z; dP[3] = dPv.w;
            if (tid > 0) dPl = g_D[(r0 - 1) * N + c0 - 1];
        }
        // left seams for zs rows r0, r0+1 and D rows r0, r0+1 (own g_D rows)
        float zsl[2] = {0.f, 0.f};
        float dl[2]  = {0.f, 0.f};
        if (tid > 0) {
            zsl[0] = Zt[r0 * N + c0 - 1] + Hc[r0 * N + c0 - 1];
            zsl[1] = Zt[(r0 + 1) * N + c0 - 1] + Hc[(r0 + 1) * N + c0 - 1];
            dl[0]  = g_D[r0 * N + c0 - 1];
            if (r0 + 1 <= N - 2) dl[1] = g_D[(r0 + 1) * N + c0 - 1];
        }

        #pragma unroll
        for (int rr = 0; rr < RPB; rr++) {
            int r = r0 + rr;
            float out[4];
            if (r == 0 || r == N - 1) {
                #pragma unroll
                for (int j = 0; j < 4; j++) out[j] = fmaxf(h[rr][j], 0.0f);
            } else {
                float4 el = ld4(&Zela[r * N + c0]);
                float elv[4] = { el.x, el.y, el.z, el.w };
                #pragma unroll
                for (int j = 0; j < 4; j++) {
                    int c = c0 + j;
                    float hh = h[rr][j];
                    if (c == 0 || c == N - 1) {
                        out[j] = fmaxf(hh, 0.0f);
                    } else {
                        float zc = zs[rr][j];
                        float zl = (j == 0) ? zsl[rr] : zs[rr][j - 1];
                        float zr = zs[rr][j + 1];
                        float zu = (rr == 0) ? zu0[j] : zs[0][j];
                        float zd = zs[rr + 1][j];
                        // D rows: up = r-1, low = r
                        float Dul = (rr == 0) ? ((j == 0) ? dPl : dP[j - 1])
                                              : ((j == 0) ? dl[0] : dv[0][j - 1]);
                        float Dur = (rr == 0) ? dP[j] : dv[0][j];
                        float Dll = (j == 0) ? dl[rr] : dv[rr][j - 1];
                        float Dlr = dv[rr][j];

                        float qxL = -(0.5f * (Dul + Dll)) * (zc - zl) / 100.0f;
                        float qxR = -(0.5f * (Dur + Dlr)) * (zr - zc) / 100.0f;
                        float qyU = -(0.5f * (Dul + Dur)) * (zc - zu) / 100.0f;
                        float qyD = -(0.5f * (Dll + Dlr)) * (zd - zc) / 100.0f;

                        float dHdt = -((qxR - qxL) / 100.0f + (qyD - qyU) / 100.0f);
                        float b = fminf(1e-3f * (zc - elv[j]), 0.3f);
                        out[j] = fmaxf(hh + dt * (dHdt + b), 0.0f);
                    }
                }
            }
            *(float4*)&Hn[r * N + c0] = make_float4(out[0], out[1], out[2], out[3]);
        }
        t += dt;

        grid_sync(++gen);
    }
    // all 32 steps done: STEPS even -> result in buf0 == d_out
}

// ---------------------------------------------------------------------------
extern "C" void kernel_launch(void* const* d_in, const int* in_sizes, int n_in,
                              void* d_out, int out_size) {
    const float* Zela  = (const float*)d_in[0];
    const float* Ztopo = (const float*)d_in[1];
    const float* Hinit = (const float*)d_in[2];
    float* out = (float*)d_out;

    float* hbuf = nullptr;
    cudaGetSymbolAddress((void**)&hbuf, g_Hbuf);

    init_kernel<<<NB, NT>>>(Hinit, out);
    glacier_persist<<<NB, NT>>>(out, hbuf, Ztopo, Zela);
}